// round 10
// baseline (speedup 1.0000x reference)
#include <cuda_runtime.h>
#include <math_constants.h>

// ---------------------------------------------------------------------------
// DetectionLoss via spatial binning. Single persistent kernel, 1184 blocks
// (8 x 148, all co-resident), monotonic-ticket grid barriers (replay-safe).
//  pass0: zero bin counts
//  passA: count anchors per (seg=lvl*16+b, 96x96 cell)
//  passB: per-segment exclusive prefix (48 blocks) -> g_off, g_cur
//  passC: fill CSR payload (packed xy + anchor idx)
//  passD: per task-warp ring search for exact (min d2, first idx), then
//         CE (warp logsumexp over 80) + L1; smem partials -> 3 atomics/block
//  finalize: last arriver reads+resets accumulators, writes out[3].
// Tie-break: 64-bit key (d2_bits<<32 | idx) minimized over ALL candidates
// within the proven search radius => first-index semantics, exact.
// ---------------------------------------------------------------------------

#define NB    16
#define NGT   128
#define NC    80
#define HW0   25600
#define HW1   6400
#define HW2   1600
#define L0TOT 409600            // 16*25600
#define L1TOT 102400            // 16*6400
#define NANCH 537600            // + 16*1600
#define GDIM  96
#define NBINS (GDIM * GDIM)     // 9216
#define NSEG  48
#define NTASK 6144
#define NBLK  1184              // 8 * 148
#define NTHR  (NBLK * 128)
#define BPT   72                // bins per thread in scan: 9216/128
#define H     0.125f

__device__ unsigned g_cnt[NSEG * NBINS];
__device__ unsigned g_off[NSEG * NBINS];
__device__ unsigned g_cur[NSEG * NBINS];
__device__ unsigned long long g_pxy[NANCH];
__device__ int g_pidx[NANCH];
__device__ float g_acc[3];      // zero-init; exch-reset each replay
__device__ unsigned g_bar;      // monotonic tickets for all grid barriers
__device__ unsigned g_bar1;     // finalize ticket

typedef unsigned long long u64;

__device__ __forceinline__ int cellc(float x) {
    int c = __float2int_rd(__fmaf_rn(x, 8.0f, 48.0f));
    return min(GDIM - 1, max(0, c));
}

__device__ __forceinline__ void decode_anchor(int i, int& lvl, int& b, int& a) {
    if (i < L0TOT)               { lvl = 0; b = i / HW0; a = i - b * HW0; }
    else if (i < L0TOT + L1TOT)  { int j = i - L0TOT; lvl = 1; b = j / HW1; a = j - b * HW1; }
    else                         { int j = i - L0TOT - L1TOT; lvl = 2; b = j / HW2; a = j - b * HW2; }
}

__device__ __forceinline__ int seg_base(int lvl, int b) {
    return (lvl == 0) ? b * HW0
         : (lvl == 1) ? L0TOT + b * HW1
                      : L0TOT + L1TOT + b * HW2;
}

__device__ __forceinline__ void grid_bar() {
    __syncthreads();
    if (threadIdx.x == 0) {
        __threadfence();
        const unsigned t = atomicAdd(&g_bar, 1u);
        const unsigned target = (t / NBLK + 1u) * NBLK;
        const volatile unsigned* vb = (const volatile unsigned*)&g_bar;
        while (*vb < target) __nanosleep(64);
        __threadfence();
    }
    __syncthreads();
}

__device__ __forceinline__ void scan_cell(int cx, int cy, int segbinbase,
                                          int sbase, float gx, float gy,
                                          int lane, u64& best) {
    if (cx < 0 || cx >= GDIM || cy < 0 || cy >= GDIM) return;
    const int bin = segbinbase + cy * GDIM + cx;
    const unsigned off = __ldg(&g_off[bin]);
    const unsigned cnt = __ldg(&g_cnt[bin]);
    for (unsigned j = lane; j < cnt; j += 32) {
        const int slot = sbase + (int)(off + j);
        const u64 xy = g_pxy[slot];
        const float ax = __uint_as_float((unsigned)xy);
        const float ay = __uint_as_float((unsigned)(xy >> 32));
        const float dx = ax - gx;
        const float dy = ay - gy;
        const float d2 = fmaf(dy, dy, dx * dx);
        const u64 key = ((u64)__float_as_uint(d2) << 32) | (unsigned)g_pidx[slot];
        if (key < best) best = key;
    }
}

__global__ void __launch_bounds__(128, 10) k_all(
    const float* __restrict__ r0, const float* __restrict__ r1,
    const float* __restrict__ r2, const float* __restrict__ c0,
    const float* __restrict__ c1, const float* __restrict__ c2,
    const float* __restrict__ gtb, const int* __restrict__ lbl,
    float* __restrict__ out) {
    __shared__ unsigned wtot[4], wpre[4];
    __shared__ float s_part[3];

    const int tid  = threadIdx.x;
    const int gtid = blockIdx.x * 128 + tid;
    const int lane = tid & 31;

    // ---- pass 0: zero counts ----
    for (int i = gtid; i < NSEG * NBINS; i += NTHR) g_cnt[i] = 0u;
    grid_bar();

    // ---- pass A: count ----
    for (int i = gtid; i < NANCH; i += NTHR) {
        int lvl, b, a;
        decode_anchor(i, lvl, b, a);
        const float* reg = (lvl == 0) ? r0 : ((lvl == 1) ? r1 : r2);
        const int HW = (lvl == 0) ? HW0 : ((lvl == 1) ? HW1 : HW2);
        const float2 p = *(const float2*)(reg + ((size_t)b * HW + a) * 4);
        const int bin = (lvl * NB + b) * NBINS + cellc(p.y) * GDIM + cellc(p.x);
        atomicAdd(&g_cnt[bin], 1u);
    }
    grid_bar();

    // ---- pass B: per-segment exclusive scan (blocks 0..47) ----
    if (blockIdx.x < NSEG) {
        const int base = blockIdx.x * NBINS + tid * BPT;
        unsigned s = 0;
        for (int k = 0; k < BPT; k++) s += g_cnt[base + k];
        unsigned v = s;
#pragma unroll
        for (int o = 1; o < 32; o <<= 1) {
            const unsigned u = __shfl_up_sync(0xFFFFFFFFu, v, o);
            if (lane >= o) v += u;
        }
        if (lane == 31) wtot[tid >> 5] = v;
        __syncthreads();
        if (tid == 0) {
            unsigned run = 0;
            for (int w2 = 0; w2 < 4; w2++) { wpre[w2] = run; run += wtot[w2]; }
        }
        __syncthreads();
        unsigned run = wpre[tid >> 5] + v - s;
        for (int k = 0; k < BPT; k++) {
            const unsigned c = g_cnt[base + k];
            g_off[base + k] = run;
            g_cur[base + k] = run;
            run += c;
        }
    }
    grid_bar();

    // ---- pass C: fill CSR ----
    for (int i = gtid; i < NANCH; i += NTHR) {
        int lvl, b, a;
        decode_anchor(i, lvl, b, a);
        const float* reg = (lvl == 0) ? r0 : ((lvl == 1) ? r1 : r2);
        const int HW = (lvl == 0) ? HW0 : ((lvl == 1) ? HW1 : HW2);
        const float2 p = *(const float2*)(reg + ((size_t)b * HW + a) * 4);
        const int bin = (lvl * NB + b) * NBINS + cellc(p.y) * GDIM + cellc(p.x);
        const unsigned pos = atomicAdd(&g_cur[bin], 1u);
        const int slot = seg_base(lvl, b) + (int)pos;
        g_pxy[slot] = ((u64)__float_as_uint(p.y) << 32) | __float_as_uint(p.x);
        g_pidx[slot] = a;
    }
    grid_bar();

    // ---- pass D: ring-search match + loss ----
    if (tid < 3) s_part[tid] = 0.0f;
    __syncthreads();

    for (int w = blockIdx.x * 4 + (tid >> 5); w < NTASK; w += NBLK * 4) {
        const int lvl = w >> 11;
        const int rr  = w & 2047;
        const int b   = rr >> 7;
        const int n   = rr & 127;
        const int segbinbase = (lvl * NB + b) * NBINS;
        const int sbase = seg_base(lvl, b);

        const float2 g = *(const float2*)(gtb + (size_t)(b * NGT + n) * 4);
        const float gx = g.x, gy = g.y;
        const float e = fmaxf(fabsf(gx) - 6.0f, 0.0f) + fmaxf(fabsf(gy) - 6.0f, 0.0f);
        const int cgx = cellc(gx);
        const int cgy = cellc(gy);

        u64 best = 0xFFFFFFFFFFFFFFFFull;
        float bestd2 = CUDART_INF_F;

        for (int r = 0; r < GDIM; r++) {
            if (r >= 2) {
                const float dmin = (float)(r - 1) * H - e;
                if (dmin > 0.0f && dmin * dmin * 0.99999f > bestd2) break;
            }
            if (r == 0) {
                scan_cell(cgx, cgy, segbinbase, sbase, gx, gy, lane, best);
            } else {
                const int x0 = cgx - r, x1 = cgx + r;
                const int y0 = cgy - r, y1 = cgy + r;
                for (int cx = x0; cx <= x1; cx++) {
                    scan_cell(cx, y0, segbinbase, sbase, gx, gy, lane, best);
                    scan_cell(cx, y1, segbinbase, sbase, gx, gy, lane, best);
                }
                for (int cy = y0 + 1; cy < y1; cy++) {
                    scan_cell(x0, cy, segbinbase, sbase, gx, gy, lane, best);
                    scan_cell(x1, cy, segbinbase, sbase, gx, gy, lane, best);
                }
            }
            // warp-reduce key (uniform best across lanes for break test)
#pragma unroll
            for (int o = 16; o; o >>= 1) {
                const u64 other = __shfl_xor_sync(0xFFFFFFFFu, best, o);
                if (other < best) best = other;
            }
            bestd2 = __uint_as_float((unsigned)(best >> 32));
        }

        const float m  = bestd2;
        const int  idx = (int)(unsigned)(best & 0xFFFFFFFFu);
        const float wt = (__fsqrt_rn(m) < 2.5f) ? 1.0f : 0.0f;

        const float* cls = (lvl == 0) ? c0 : ((lvl == 1) ? c1 : c2);
        const float* reg = (lvl == 0) ? r0 : ((lvl == 1) ? r1 : r2);
        const int    HW  = (lvl == 0) ? HW0 : ((lvl == 1) ? HW1 : HW2);

        // CE via warp logsumexp over 80 logits
        const float* row = cls + ((size_t)b * HW + idx) * NC;
        const float x0 = row[lane];
        const float x1 = row[lane + 32];
        const float x2 = (lane < 16) ? row[lane + 64] : -CUDART_INF_F;

        float mx = fmaxf(fmaxf(x0, x1), x2);
#pragma unroll
        for (int o = 16; o; o >>= 1) mx = fmaxf(mx, __shfl_xor_sync(0xFFFFFFFFu, mx, o));

        float s = expf(x0 - mx) + expf(x1 - mx) + ((lane < 16) ? expf(x2 - mx) : 0.0f);

        const int label = lbl[rr];
        float xl = 0.0f;
        if (lane == label)           xl = x0;
        else if (lane + 32 == label) xl = x1;
        else if (lane + 64 == label) xl = x2;

#pragma unroll
        for (int o = 16; o; o >>= 1) {
            s  += __shfl_xor_sync(0xFFFFFFFFu, s, o);
            xl += __shfl_xor_sync(0xFFFFFFFFu, xl, o);
        }

        if (lane == 0) {
            const float ce = (mx + logf(s)) - xl;
            const float4 p  = *(const float4*)(reg + ((size_t)b * HW + idx) * 4);
            const float4 gg = *(const float4*)(gtb + (size_t)(b * NGT + n) * 4);
            const float l1 = fabsf(p.x - gg.x) + fabsf(p.y - gg.y) +
                             fabsf(p.z - gg.z) + fabsf(p.w - gg.w);
            atomicAdd(&s_part[0], ce * wt);
            atomicAdd(&s_part[1], l1 * wt);
            atomicAdd(&s_part[2], wt);
        }
    }

    // ---- block partial -> global; last arriver finalizes ----
    __syncthreads();
    if (tid == 0) {
        atomicAdd(&g_acc[0], s_part[0]);
        atomicAdd(&g_acc[1], s_part[1]);
        atomicAdd(&g_acc[2], s_part[2]);
        __threadfence();
        const unsigned t2 = atomicAdd(&g_bar1, 1u);
        if (t2 % NBLK == NBLK - 1u) {
            const float a0 = atomicExch(&g_acc[0], 0.0f);
            const float a1 = atomicExch(&g_acc[1], 0.0f);
            const float np = atomicExch(&g_acc[2], 0.0f);
            const float denom = fmaxf(np, 1.0f);
            out[0] = a0 / denom;
            out[1] = a1 / denom;
            out[2] = np;
        }
    }
}

// ---------------------------------------------------------------------------
extern "C" void kernel_launch(void* const* d_in, const int* in_sizes, int n_in,
                              void* d_out, int out_size) {
    const float* c[3] = {0, 0, 0};
    const float* r[3] = {0, 0, 0};
    const float* gtb  = 0;
    const int*   lbl  = 0;
    for (int i = 0; i < n_in; i++) {
        switch (in_sizes[i]) {
            case NB * HW0 * NC: c[0] = (const float*)d_in[i]; break;
            case NB * HW1 * NC: c[1] = (const float*)d_in[i]; break;
            case NB * HW2 * NC: c[2] = (const float*)d_in[i]; break;
            case NB * HW0 * 4:  r[0] = (const float*)d_in[i]; break;
            case NB * HW1 * 4:  r[1] = (const float*)d_in[i]; break;
            case NB * HW2 * 4:  r[2] = (const float*)d_in[i]; break;
            case NB * NGT * 4:  gtb  = (const float*)d_in[i]; break;
            case NB * NGT:      lbl  = (const int*)d_in[i];   break;
        }
    }

    k_all<<<NBLK, 128>>>(r[0], r[1], r[2], c[0], c[1], c[2], gtb, lbl,
                         (float*)d_out);
}